// round 12
// baseline (speedup 1.0000x reference)
#include <cuda_runtime.h>
#include <cuda_bf16.h>
#include <math.h>
#include <cstdint>

// ---- problem dims ----
#define B_   64
#define S_   200
#define T_   32
#define V_   50000
#define E_   128
#define C_   128
#define H_   100
#define OUT_ 104
#define NT_  (B_*S_)  // 12800 trees
#define N_   (NT_*T_) // 409600 nodes
#define MPAD 50048    // V_ padded to 128-row tiles (391*128)

typedef unsigned long long u64;

// ---- packed f32x2 helpers ----
#define FMA2(d, a, b, c) \
    asm("fma.rn.f32x2 %0, %1, %2, %3;" : "=l"(d) : "l"(a), "l"(b), "l"(c))
#define ADD2(d, a, b) \
    asm("add.rn.f32x2 %0, %1, %2;" : "=l"(d) : "l"(a), "l"(b))

__device__ __forceinline__ float2 unpack2(u64 v) {
    unsigned lo, hi;
    asm("mov.b64 {%0, %1}, %2;" : "=r"(lo), "=r"(hi) : "l"(v));
    return make_float2(__uint_as_float(lo), __uint_as_float(hi));
}
__device__ __forceinline__ float tanh_fast(float x) {
    return 1.0f - 2.0f * __frcp_rn(__expf(2.0f * x) + 1.0f);
}

// ---- warp MMA helpers (sm_80+ features, legal at compute_103) ----
#define LDSM4(r, addr) \
    asm volatile("ldmatrix.sync.aligned.m8n8.x4.shared.b16 {%0,%1,%2,%3}, [%4];" \
        : "=r"((r)[0]), "=r"((r)[1]), "=r"((r)[2]), "=r"((r)[3]) : "r"(addr))

#define MMA16816(c, a, b) \
    asm volatile("mma.sync.aligned.m16n8k16.row.col.f32.bf16.bf16.f32 " \
        "{%0,%1,%2,%3}, {%4,%5,%6,%7}, {%8,%9}, {%0,%1,%2,%3};" \
        : "+f"((c)[0]), "+f"((c)[1]), "+f"((c)[2]), "+f"((c)[3]) \
        : "r"((a)[0]), "r"((a)[1]), "r"((a)[2]), "r"((a)[3]), \
          "r"((b)[0]), "r"((b)[1]))

__device__ __forceinline__ uint32_t smem_to_u32(const void* p) {
    uint32_t a;
    asm("{ .reg .u64 t; cvta.to.shared.u64 t, %1; cvt.u32.u64 %0, t; }"
        : "=r"(a) : "l"(p));
    return a;
}

// ---- device scratch (static globals; no runtime allocation) ----
// __align__(16): these are read through uint4/float4 casts.
__device__ __align__(16) float g_ctable[V_ * C_];
__device__ __align__(16) float g_treevec[NT_ * C_];
__device__ __align__(16) float g_gx[NT_ * 600];
__device__ __align__(16) float g_poolT[200 * 64];
__device__ __align__(16) __nv_bfloat16 g_Ahi[MPAD * 128], g_Alo[MPAD * 128];
__device__ __align__(16) __nv_bfloat16 g_tvhi[NT_ * 128], g_tvlo[NT_ * 128];
__device__ __align__(16) __nv_bfloat16 g_Bhi[768 * 128], g_Blo[768 * 128];
__device__ __align__(16) float g_biasC[768];   // blin|bihf|bihb

// ============================================================================
// Pre-convert combined B weights + bias -> bf16 hi/lo (rows: 0-127 w_lin,
// 128-427 w_ih_f, 428-727 w_ih_b, 728-767 zero pad).
// ============================================================================
__global__ void build_B_kernel(
    const float* __restrict__ wlin, const float* __restrict__ wihf,
    const float* __restrict__ wihb,
    const float* __restrict__ blin, const float* __restrict__ bihf,
    const float* __restrict__ bihb)
{
    int idx = blockIdx.x * blockDim.x + threadIdx.x;
    if (idx < 768 * 128) {
        int r = idx >> 7, k = idx & 127;
        float x = 0.f;
        if (r < 128)      x = wlin[r * 128 + k];
        else if (r < 428) x = wihf[(r - 128) * 128 + k];
        else if (r < 728) x = wihb[(r - 428) * 128 + k];
        __nv_bfloat16 h = __float2bfloat16(x);
        g_Bhi[idx] = h;
        g_Blo[idx] = __float2bfloat16(x - __bfloat162float(h));
    }
    if (idx < 768) {
        float bb = 0.f;
        if (idx < 128)      bb = blin[idx];
        else if (idx < 428) bb = bihf[idx - 128];
        else if (idx < 728) bb = bihb[idx - 428];
        g_biasC[idx] = bb;
    }
}

// ============================================================================
// Split f32 matrix into bf16 hi/lo. mode 0: src0 (emb, real device ptr) ->
// g_Ahi/g_Alo zero-padded to MPAD rows. mode 1: g_treevec (selected HERE in
// device code — host code must never take a __device__ global's address) ->
// g_tvhi/g_tvlo. One float4 per thread.
// ============================================================================
__global__ void convert_split_kernel(const float* __restrict__ src0,
                                     int n_src4, int n_tot4, int mode)
{
    int i = blockIdx.x * blockDim.x + threadIdx.x;
    if (i >= n_tot4) return;
    const float* src = (mode == 1) ? g_treevec : src0;
    __nv_bfloat16* dh = mode ? g_tvhi : g_Ahi;
    __nv_bfloat16* dl = mode ? g_tvlo : g_Alo;
    float4 v = make_float4(0.f, 0.f, 0.f, 0.f);
    if (i < n_src4) v = ((const float4*)src)[i];
    float vs[4] = {v.x, v.y, v.z, v.w};
    __nv_bfloat16 hv[4], lv[4];
    #pragma unroll
    for (int k = 0; k < 4; k++) {
        hv[k] = __float2bfloat16(vs[k]);
        lv[k] = __float2bfloat16(vs[k] - __bfloat162float(hv[k]));
    }
    __nv_bfloat162* dh2 = (__nv_bfloat162*)(dh + 4 * (size_t)i);
    __nv_bfloat162* dl2 = (__nv_bfloat162*)(dl + 4 * (size_t)i);
    dh2[0] = __nv_bfloat162(hv[0], hv[1]);
    dh2[1] = __nv_bfloat162(hv[2], hv[3]);
    dl2[0] = __nv_bfloat162(lv[0], lv[1]);
    dl2[1] = __nv_bfloat162(lv[2], lv[3]);
}

// ============================================================================
// HMMA GEMM: tile M=128, N=128, K=128, NT (A row-major [m][k], B [n][k]).
// bf16 hi/lo 3-term: AhBh + AhBl + AlBh, f32 accumulation.
// 256 threads = 8 warps laid out 4(m) x 2(n); warp tile 32m x 64n.
// Smem: 4 tiles of 128x128 bf16, 256B rows, 16B-chunk XOR swizzle
// (chunk ^ (row&7)) -> conflict-free ldmatrix at 256B stride.
// mode 0: A=g_Ahi/lo (emb), B rows 0..127 (w_lin),  out g_ctable (+bias).
// mode 1: A=g_tvhi/lo,      B rows 128..727 (w_ih), out g_gx scattered (+bias).
// ============================================================================
#define TILE_BYTES 32768
#define SM_TOT (4 * TILE_BYTES)

__device__ __forceinline__ void copy_tile_sw(char* dst, const __nv_bfloat16* src,
                                             int tid) {
    const uint4* s = (const uint4*)src;
    #pragma unroll
    for (int i = 0; i < 8; i++) {
        int chunk = tid + i * 256;        // 0..2047 (16B chunks of 128x128 bf16)
        int row = chunk >> 4, cc = chunk & 15;
        uint4 v = s[chunk];
        *(uint4*)(dst + row * 256 + ((cc ^ (row & 7)) << 4)) = v;
    }
}

__global__ void __launch_bounds__(256) mma_gemm_kernel(int mode)
{
    extern __shared__ char smem[];
    char* sAh = smem;
    char* sAl = smem + TILE_BYTES;
    char* sBh = smem + 2 * TILE_BYTES;
    char* sBl = smem + 3 * TILE_BYTES;

    const int tid  = threadIdx.x;
    const int wid  = tid >> 5;
    const int lane = tid & 31;
    const int mt   = blockIdx.y, ntile = blockIdx.x;
    const int m0   = mt * 128;
    const int brow0 = (mode == 0 ? 0 : 128) + ntile * 128;

    const __nv_bfloat16* aH = mode ? g_tvhi : g_Ahi;
    const __nv_bfloat16* aL = mode ? g_tvlo : g_Alo;
    copy_tile_sw(sAh, aH + (size_t)m0 * 128, tid);
    copy_tile_sw(sAl, aL + (size_t)m0 * 128, tid);
    copy_tile_sw(sBh, g_Bhi + (size_t)brow0 * 128, tid);
    copy_tile_sw(sBl, g_Blo + (size_t)brow0 * 128, tid);
    __syncthreads();

    const uint32_t uAh = smem_to_u32(sAh), uAl = smem_to_u32(sAl);
    const uint32_t uBh = smem_to_u32(sBh), uBl = smem_to_u32(sBl);

    const int wm = (wid & 3) * 32;   // warp m origin (0,32,64,96)
    const int wn = (wid >> 2) * 64;  // warp n origin (0,64)

    float c[2][8][4];
    #pragma unroll
    for (int i = 0; i < 2; i++)
        #pragma unroll
        for (int j = 0; j < 8; j++)
            #pragma unroll
            for (int q = 0; q < 4; q++) c[i][j][q] = 0.f;

    // ldmatrix address components (lane-dependent, k-independent parts)
    const int arow = wm + (lane & 15);            // + mi*16
    const int ach  = lane >> 4;                   // +k chunk
    const int brow = wn + (lane & 7) + ((lane >> 4) << 3);  // + np*16
    const int bch  = (lane >> 3) & 1;

    #pragma unroll
    for (int ks = 0; ks < 8; ks++) {
        const int kc = ks * 2;                    // base 16B-chunk of this k16
        uint32_t ah[2][4], al[2][4], bh[4][4], bl[4][4];
        #pragma unroll
        for (int mi = 0; mi < 2; mi++) {
            int r = arow + mi * 16;
            uint32_t off = r * 256 + (((kc + ach) ^ (r & 7)) << 4);
            LDSM4(ah[mi], uAh + off);
            LDSM4(al[mi], uAl + off);
        }
        #pragma unroll
        for (int np = 0; np < 4; np++) {          // each covers 16 n
            int r = brow + np * 16;
            uint32_t off = r * 256 + (((kc + bch) ^ (r & 7)) << 4);
            LDSM4(bh[np], uBh + off);
            LDSM4(bl[np], uBl + off);
        }
        #pragma unroll
        for (int mi = 0; mi < 2; mi++)
            #pragma unroll
            for (int nj = 0; nj < 8; nj++) {
                uint32_t bfh[2] = { bh[nj >> 1][(nj & 1) * 2],
                                    bh[nj >> 1][(nj & 1) * 2 + 1] };
                uint32_t bfl[2] = { bl[nj >> 1][(nj & 1) * 2],
                                    bl[nj >> 1][(nj & 1) * 2 + 1] };
                MMA16816(c[mi][nj], ah[mi], bfh);   // Ah*Bh
                MMA16816(c[mi][nj], ah[mi], bfl);   // Ah*Bl
                MMA16816(c[mi][nj], al[mi], bfh);   // Al*Bh
            }
    }

    // ---- epilogue: c-frag map: rows gr, gr+8; cols 2*(lane&3) ----
    const int gr = lane >> 2;
    const int cp = (lane & 3) * 2;
    #pragma unroll
    for (int mi = 0; mi < 2; mi++) {
        #pragma unroll
        for (int nj = 0; nj < 8; nj++) {
            int n = wn + nj * 8 + cp;                    // tile-local col
            int ng = ntile * 128 + n;                    // global col
            if (mode == 1 && ng >= 600) continue;
            float b0 = g_biasC[(mode ? 128 : 0) + ng];
            float b1 = g_biasC[(mode ? 128 : 0) + ng + 1];
            #pragma unroll
            for (int hrow = 0; hrow < 2; hrow++) {
                int m = m0 + wm + mi * 16 + gr + hrow * 8;
                float2 v = make_float2(c[mi][nj][hrow * 2] + b0,
                                       c[mi][nj][hrow * 2 + 1] + b1);
                if (mode == 0) {
                    if (m < V_) *(float2*)(g_ctable + (size_t)m * 128 + ng) = v;
                } else {
                    int s = m % 200, bb = m / 200;
                    *(float2*)(g_gx + (size_t)(s * 64 + bb) * 600 + ng) = v;
                }
            }
        }
    }
}

// ============================================================================
// Tree encode: gather + fixed-topology subtree sums + max pool.
// ============================================================================
__global__ void __launch_bounds__(128) tree_kernel(const int* __restrict__ tokens)
{
    const int tree = blockIdx.x;
    const int c = threadIdx.x;
    __shared__ int tok[32];
    if (c < 32) tok[c] = tokens[tree * 32 + c];
    __syncthreads();

    float v[32];
    #pragma unroll
    for (int i = 0; i < 32; i++)
        v[i] = g_ctable[(size_t)tok[i] * 128 + c];

    #pragma unroll
    for (int i = 31; i >= 1; i--)
        v[(i - 1) >> 1] += v[i];

    float m = v[0];
    #pragma unroll
    for (int i = 1; i < 32; i++) m = fmaxf(m, v[i]);

    g_treevec[(size_t)tree * 128 + c] = m;
}

// ============================================================================
// GRU recurrence (R2 layout — best measured) + tanh_fast.
// 128 blocks = (dir, batch). Thread j<300 owns W_hh row j as 50 packed f32x2
// in registers; h broadcast from smem via LDS.128. Time-max folded in.
// ============================================================================
__global__ void __launch_bounds__(320) gru_kernel(
    const float* __restrict__ whh_f, const float* __restrict__ whh_b,
    const float* __restrict__ bhh_f, const float* __restrict__ bhh_b)
{
    const int blk = blockIdx.x;     // 0..127
    const int dir = blk >> 6;
    const int b   = blk & 63;
    const int j   = threadIdx.x;    // active < 300

    __shared__ __align__(16) float h_s[100];
    __shared__ float gh_s[300];
    __shared__ float gxn_s[100];

    const float* __restrict__ whh = dir ? whh_b : whh_f;
    const float* __restrict__ bhh = dir ? bhh_b : bhh_f;

    u64 w2[50];
    float bh = 0.f;
    if (j < 300) {
        const u64* wrow = (const u64*)(whh + j * 100);
        #pragma unroll
        for (int k = 0; k < 50; k++) w2[k] = wrow[k];
        bh = bhh[j];
    }
    if (j < 100) h_s[j] = 0.f;
    float mx = -1e30f;

    int s0 = dir ? 199 : 0;
    float gx_next = 0.f;
    if (j < 300) gx_next = g_gx[(size_t)(s0 * 64 + b) * 600 + dir * 300 + j];
    __syncthreads();

    const ulonglong2* h2 = (const ulonglong2*)h_s;

    #pragma unroll 1
    for (int sp = 0; sp < 200; sp++) {
        float gxv = gx_next;
        if (sp < 199 && j < 300) {
            int sn = dir ? (198 - sp) : (sp + 1);
            gx_next = g_gx[(size_t)(sn * 64 + b) * 600 + dir * 300 + j];
        }
        if (j < 300) {
            u64 a0 = 0ull, a1 = 0ull, a2 = 0ull, a3 = 0ull;
            #pragma unroll
            for (int k = 0; k < 25; k++) {
                ulonglong2 hv = h2[k];
                if (k & 1) {
                    FMA2(a2, w2[2*k],   hv.x, a2);
                    FMA2(a3, w2[2*k+1], hv.y, a3);
                } else {
                    FMA2(a0, w2[2*k],   hv.x, a0);
                    FMA2(a1, w2[2*k+1], hv.y, a1);
                }
            }
            ADD2(a0, a0, a2);
            ADD2(a1, a1, a3);
            ADD2(a0, a0, a1);
            float2 f = unpack2(a0);
            float acc = f.x + f.y + bh;
            if (j < 200) {
                float x = gxv + acc;
                gh_s[j] = 1.f / (1.f + __expf(-x));
            } else {
                gh_s[j] = acc;
                gxn_s[j - 200] = gxv;
            }
        }
        __syncthreads();
        if (j < 100) {
            float r = gh_s[j];
            float z = gh_s[j + 100];
            float n = tanh_fast(gxn_s[j] + r * gh_s[j + 200]);
            float hn = fmaf(z, h_s[j] - n, n);
            h_s[j] = hn;
            mx = fmaxf(mx, hn);
        }
        __syncthreads();
    }

    if (j < 100) g_poolT[(dir * 100 + j) * 64 + b] = mx;
}

// ============================================================================
// Final FC: out[b,o] = pool[b,:] . fc_w[o,:] + fc_b[o]
// ============================================================================
__global__ void __launch_bounds__(64) fc_kernel(
    const float* __restrict__ fcw, const float* __restrict__ fcb,
    float* __restrict__ out)
{
    const int o = blockIdx.x;
    const int b = threadIdx.x;
    __shared__ float w_s[200];
    for (int k = b; k < 200; k += 64) w_s[k] = fcw[o * 200 + k];
    __syncthreads();

    float acc = fcb[o];
    #pragma unroll
    for (int k = 0; k < 200; k++)
        acc = fmaf(w_s[k], g_poolT[k * 64 + b], acc);

    out[b * 104 + o] = acc;
}

// ============================================================================
extern "C" void kernel_launch(void* const* d_in, const int* in_sizes, int n_in,
                              void* d_out, int out_size)
{
    const int*   tokens = (const int*)  d_in[0];
    const float* emb    = (const float*)d_in[4];
    const float* w_lin  = (const float*)d_in[5];
    const float* b_lin  = (const float*)d_in[6];
    const float* w_ih_f = (const float*)d_in[7];
    const float* w_hh_f = (const float*)d_in[8];
    const float* b_ih_f = (const float*)d_in[9];
    const float* b_hh_f = (const float*)d_in[10];
    const float* w_ih_b = (const float*)d_in[11];
    const float* w_hh_b = (const float*)d_in[12];
    const float* b_ih_b = (const float*)d_in[13];
    const float* b_hh_b = (const float*)d_in[14];
    const float* fc_w   = (const float*)d_in[15];
    const float* fc_b   = (const float*)d_in[16];
    float* out = (float*)d_out;

    cudaFuncSetAttribute(mma_gemm_kernel,
                         cudaFuncAttributeMaxDynamicSharedMemorySize, SM_TOT);

    // Pre-convert weights (B) and emb (A) to bf16 hi/lo
    build_B_kernel<<<384, 256>>>(w_lin, w_ih_f, w_ih_b, b_lin, b_ih_f, b_ih_b);
    {
        int tot4 = MPAD * 128 / 4, src4 = V_ * 128 / 4;
        convert_split_kernel<<<(tot4 + 255) / 256, 256>>>(emb, src4, tot4, 0);
    }
    // K1: c_table = emb @ w_lin.T + b_lin  (HMMA, 391 m-tiles x 1 n-tile)
    mma_gemm_kernel<<<dim3(1, 391), 256, SM_TOT>>>(0);

    // K2: gather + subtree sums + per-tree max pool
    tree_kernel<<<NT_, 128>>>(tokens);

    // Convert treevec (source selected in device code), then K3: input gates
    {
        int tot4 = NT_ * 128 / 4;
        convert_split_kernel<<<(tot4 + 255) / 256, 256>>>(nullptr, tot4, tot4, 1);
    }
    mma_gemm_kernel<<<dim3(5, 100), 256, SM_TOT>>>(1);

    // K4: serial recurrence
    gru_kernel<<<128, 320>>>(w_hh_f, w_hh_b, b_hh_f, b_hh_b);

    // K5: final FC
    fc_kernel<<<104, 64>>>(fc_w, fc_b, out);
}

// round 13
// speedup vs baseline: 1.2566x; 1.2566x over previous
#include <cuda_runtime.h>
#include <math.h>

// ---- problem dims ----
#define B_   64
#define S_   200
#define T_   32
#define V_   50000
#define E_   128
#define C_   128
#define H_   100
#define OUT_ 104
#define NT_  (B_*S_)  // 12800 trees
#define N_   (NT_*T_) // 409600 nodes

typedef unsigned long long u64;

// ---- packed f32x2 helpers (Blackwell FFMA2 path) ----
#define FMA2(d, a, b, c) \
    asm("fma.rn.f32x2 %0, %1, %2, %3;" : "=l"(d) : "l"(a), "l"(b), "l"(c))
#define ADD2(d, a, b) \
    asm("add.rn.f32x2 %0, %1, %2;" : "=l"(d) : "l"(a), "l"(b))

__device__ __forceinline__ u64 dup2(float x) {
    u64 r;
    asm("mov.b64 %0, {%1, %1};" : "=l"(r) : "r"(__float_as_uint(x)));
    return r;
}
__device__ __forceinline__ float2 unpack2(u64 v) {
    unsigned lo, hi;
    asm("mov.b64 {%0, %1}, %2;" : "=r"(lo), "=r"(hi) : "l"(v));
    return make_float2(__uint_as_float(lo), __uint_as_float(hi));
}
// fast nonlinearities via EX2/RCP MUFUs (~1e-6 accuracy, correct saturation)
__device__ __forceinline__ float tanh_fast(float x) {
    return 1.0f - 2.0f * __frcp_rn(__expf(2.0f * x) + 1.0f);
}
__device__ __forceinline__ float sigmoid_fast(float x) {
    return __frcp_rn(1.0f + __expf(-x));
}

// ---- device scratch (no allocations allowed) ----
__device__ __align__(16) float g_ctable[V_ * C_];   // W*emb(v)+b per vocab entry
__device__ __align__(16) float g_treevec[NT_ * C_]; // per-tree max-pooled hidden
__device__ __align__(16) float g_gx[NT_ * 600];     // [s*64+b][600] input gates
__device__ __align__(16) float g_poolT[200 * 64];   // [2H][B] transposed pool

// ============================================================================
// GEMM (NT): C[m,n] = sum_k A[m,k]*B[n,k] + bias[n].  K fixed at 128.
// BM=128, BN=128, BK=32, 256 threads (16x16), 8m x 8n per thread,
// f32x2-packed along m (32 packed accumulators). dup on ALU pipe overlaps
// the FMA pipe -> ~80% FFMA2 issue density.
// mode 0: A=A_in (emb), out -> g_ctable[m*128+n]
// mode 1: A=g_treevec, B=w_ih_f/w_ih_b split at 300, out -> g_gx scattered
// ============================================================================
__global__ void __launch_bounds__(256) gemm_nt_kernel(
    const float* __restrict__ A_in,
    const float* __restrict__ B1, const float* __restrict__ B2, int nsplit,
    int Ncols,
    const float* __restrict__ bias1, const float* __restrict__ bias2,
    int M, int mode)
{
    __shared__ __align__(16) float As[32][132];   // k-major, 128 m cols (+pad)
    __shared__ __align__(16) float Bs[32][132];   // k-major, 128 n cols (+pad)

    const float* __restrict__ A = (mode == 0) ? A_in : g_treevec;

    const int m0 = blockIdx.y * 128;
    const int n0 = blockIdx.x * 128;
    const int tid = threadIdx.x;
    const int tx = tid & 15;       // n: 8 per thread
    const int ty = tid >> 4;       // m: 8 per thread

    u64 acc[4][8];                 // [m-pair][n]
    #pragma unroll
    for (int i = 0; i < 4; i++)
        #pragma unroll
        for (int j = 0; j < 8; j++) acc[i][j] = 0ull;

    for (int k0 = 0; k0 < 128; k0 += 32) {
        // ---- A tile: 128 rows x 32 k, transposed to k-major ----
        #pragma unroll
        for (int i = 0; i < 4; i++) {
            int f   = tid + i * 256;   // 0..1023 float4 slots
            int row = f >> 3;          // 0..127
            int kq  = f & 7;
            float4 v = make_float4(0.f, 0.f, 0.f, 0.f);
            int m = m0 + row;
            if (m < M) v = *(const float4*)(A + (size_t)m * 128 + k0 + kq * 4);
            As[kq*4+0][row] = v.x; As[kq*4+1][row] = v.y;
            As[kq*4+2][row] = v.z; As[kq*4+3][row] = v.w;
        }
        // ---- B tile: 128 rows x 32 k ----
        #pragma unroll
        for (int i = 0; i < 4; i++) {
            int f   = tid + i * 256;
            int row = f >> 3;          // 0..127
            int kq  = f & 7;
            float4 v = make_float4(0.f, 0.f, 0.f, 0.f);
            int n = n0 + row;
            if (n < Ncols) {
                const float* Bp = (n < nsplit) ? (B1 + (size_t)n * 128)
                                               : (B2 + (size_t)(n - nsplit) * 128);
                v = *(const float4*)(Bp + k0 + kq * 4);
            }
            Bs[kq*4+0][row] = v.x; Bs[kq*4+1][row] = v.y;
            Bs[kq*4+2][row] = v.z; Bs[kq*4+3][row] = v.w;
        }
        __syncthreads();

        #pragma unroll
        for (int kk = 0; kk < 32; kk++) {
            // a: 8 m-values as 4 packed pairs (2 x LDS.128)
            ulonglong2 ap0 = *(const ulonglong2*)&As[kk][ty * 8];
            ulonglong2 ap1 = *(const ulonglong2*)&As[kk][ty * 8 + 4];
            u64 ap[4] = { ap0.x, ap0.y, ap1.x, ap1.y };
            // b: 8 scalars (2 x LDS.128), duplicated on ALU pipe
            float4 b0 = *(const float4*)&Bs[kk][tx * 8];
            float4 b1 = *(const float4*)&Bs[kk][tx * 8 + 4];
            u64 bd[8] = { dup2(b0.x), dup2(b0.y), dup2(b0.z), dup2(b0.w),
                          dup2(b1.x), dup2(b1.y), dup2(b1.z), dup2(b1.w) };
            #pragma unroll
            for (int mp = 0; mp < 4; mp++)
                #pragma unroll
                for (int jj = 0; jj < 8; jj++)
                    FMA2(acc[mp][jj], ap[mp], bd[jj], acc[mp][jj]);
        }
        __syncthreads();
    }

    // ---- epilogue: two float4 stores per row ----
    int nbase = n0 + tx * 8;
    // column-chunk validity (Ncols % 8 == 0 in all uses: 128, 600+pad via mask)
    bool ok0 = (nbase < Ncols);
    bool ok1 = (nbase + 4 < Ncols);
    float bias[8];
    #pragma unroll
    for (int jj = 0; jj < 8; jj++) {
        int n = nbase + jj;
        bias[jj] = 0.f;
        if (n < Ncols)
            bias[jj] = (n < nsplit) ? bias1[n] : bias2[n - nsplit];
    }
    #pragma unroll
    for (int mp = 0; mp < 4; mp++) {
        float2 c[8];
        #pragma unroll
        for (int jj = 0; jj < 8; jj++) c[jj] = unpack2(acc[mp][jj]);
        float4 lo0 = make_float4(c[0].x + bias[0], c[1].x + bias[1],
                                 c[2].x + bias[2], c[3].x + bias[3]);
        float4 lo1 = make_float4(c[4].x + bias[4], c[5].x + bias[5],
                                 c[6].x + bias[6], c[7].x + bias[7]);
        float4 hi0 = make_float4(c[0].y + bias[0], c[1].y + bias[1],
                                 c[2].y + bias[2], c[3].y + bias[3]);
        float4 hi1 = make_float4(c[4].y + bias[4], c[5].y + bias[5],
                                 c[6].y + bias[6], c[7].y + bias[7]);
        int m = m0 + ty * 8 + 2 * mp;
        #pragma unroll
        for (int half = 0; half < 2; half++) {
            int mm = m + half;
            if (mm >= M) continue;
            float4 r0 = half ? hi0 : lo0;
            float4 r1 = half ? hi1 : lo1;
            if (mode == 0) {
                float* p = g_ctable + (size_t)mm * 128 + nbase;
                if (ok0) *(float4*)(p)     = r0;
                if (ok1) *(float4*)(p + 4) = r1;
            } else {
                int s = mm % 200;     // tree mm = b*200 + s
                int b = mm / 200;
                float* p = g_gx + (size_t)(s * 64 + b) * 600 + nbase;
                if (ok0) *(float4*)(p)     = r0;
                if (ok1) *(float4*)(p + 4) = r1;
            }
        }
    }
}

// ============================================================================
// Tree encode: gather + fixed-topology subtree sums + max pool.
// ============================================================================
__global__ void __launch_bounds__(128) tree_kernel(const int* __restrict__ tokens)
{
    const int tree = blockIdx.x;
    const int c = threadIdx.x;
    __shared__ int tok[32];
    if (c < 32) tok[c] = tokens[tree * 32 + c];
    __syncthreads();

    float v[32];
    #pragma unroll
    for (int i = 0; i < 32; i++)
        v[i] = g_ctable[(size_t)tok[i] * 128 + c];

    #pragma unroll
    for (int i = 31; i >= 1; i--)
        v[(i - 1) >> 1] += v[i];

    float m = v[0];
    #pragma unroll
    for (int i = 1; i < 32; i++) m = fmaxf(m, v[i]);

    g_treevec[(size_t)tree * 128 + c] = m;
}

// ============================================================================
// GRU recurrence (R2 layout — best measured) + MUFU-only nonlinearities.
// 128 blocks = (dir, batch). Thread j<300 owns W_hh row j as 50 packed f32x2
// in registers; h broadcast from smem via LDS.128. Time-max folded in.
// ============================================================================
__global__ void __launch_bounds__(320) gru_kernel(
    const float* __restrict__ whh_f, const float* __restrict__ whh_b,
    const float* __restrict__ bhh_f, const float* __restrict__ bhh_b)
{
    const int blk = blockIdx.x;     // 0..127
    const int dir = blk >> 6;
    const int b   = blk & 63;
    const int j   = threadIdx.x;    // active < 300

    __shared__ __align__(16) float h_s[100];
    __shared__ float gh_s[300];
    __shared__ float gxn_s[100];

    const float* __restrict__ whh = dir ? whh_b : whh_f;
    const float* __restrict__ bhh = dir ? bhh_b : bhh_f;

    u64 w2[50];
    float bh = 0.f;
    if (j < 300) {
        const u64* wrow = (const u64*)(whh + j * 100);
        #pragma unroll
        for (int k = 0; k < 50; k++) w2[k] = wrow[k];
        bh = bhh[j];
    }
    if (j < 100) h_s[j] = 0.f;
    float mx = -1e30f;

    int s0 = dir ? 199 : 0;
    float gx_next = 0.f;
    if (j < 300) gx_next = g_gx[(size_t)(s0 * 64 + b) * 600 + dir * 300 + j];
    __syncthreads();

    const ulonglong2* h2 = (const ulonglong2*)h_s;

    #pragma unroll 1
    for (int sp = 0; sp < 200; sp++) {
        float gxv = gx_next;
        if (sp < 199 && j < 300) {
            int sn = dir ? (198 - sp) : (sp + 1);
            gx_next = g_gx[(size_t)(sn * 64 + b) * 600 + dir * 300 + j];
        }
        if (j < 300) {
            u64 a0 = 0ull, a1 = 0ull, a2 = 0ull, a3 = 0ull;
            #pragma unroll
            for (int k = 0; k < 25; k++) {
                ulonglong2 hv = h2[k];
                if (k & 1) {
                    FMA2(a2, w2[2*k],   hv.x, a2);
                    FMA2(a3, w2[2*k+1], hv.y, a3);
                } else {
                    FMA2(a0, w2[2*k],   hv.x, a0);
                    FMA2(a1, w2[2*k+1], hv.y, a1);
                }
            }
            ADD2(a0, a0, a2);
            ADD2(a1, a1, a3);
            ADD2(a0, a0, a1);
            float2 f = unpack2(a0);
            float acc = f.x + f.y + bh;
            if (j < 200) {
                gh_s[j] = sigmoid_fast(gxv + acc);   // r,z rows
            } else {
                gh_s[j] = acc;                       // raw hn
                gxn_s[j - 200] = gxv;
            }
        }
        __syncthreads();
        if (j < 100) {
            float r = gh_s[j];
            float z = gh_s[j + 100];
            float n = tanh_fast(gxn_s[j] + r * gh_s[j + 200]);
            float hn = fmaf(z, h_s[j] - n, n);       // (1-z)n + z h
            h_s[j] = hn;
            mx = fmaxf(mx, hn);
        }
        __syncthreads();
    }

    if (j < 100) g_poolT[(dir * 100 + j) * 64 + b] = mx;
}

// ============================================================================
// Final FC: out[b,o] = pool[b,:] . fc_w[o,:] + fc_b[o]
// ============================================================================
__global__ void __launch_bounds__(64) fc_kernel(
    const float* __restrict__ fcw, const float* __restrict__ fcb,
    float* __restrict__ out)
{
    const int o = blockIdx.x;
    const int b = threadIdx.x;
    __shared__ float w_s[200];
    for (int k = b; k < 200; k += 64) w_s[k] = fcw[o * 200 + k];
    __syncthreads();

    float acc = fcb[o];
    #pragma unroll
    for (int k = 0; k < 200; k++)
        acc = fmaf(w_s[k], g_poolT[k * 64 + b], acc);

    out[b * 104 + o] = acc;
}

// ============================================================================
extern "C" void kernel_launch(void* const* d_in, const int* in_sizes, int n_in,
                              void* d_out, int out_size)
{
    const int*   tokens = (const int*)  d_in[0];
    const float* emb    = (const float*)d_in[4];
    const float* w_lin  = (const float*)d_in[5];
    const float* b_lin  = (const float*)d_in[6];
    const float* w_ih_f = (const float*)d_in[7];
    const float* w_hh_f = (const float*)d_in[8];
    const float* b_ih_f = (const float*)d_in[9];
    const float* b_hh_f = (const float*)d_in[10];
    const float* w_ih_b = (const float*)d_in[11];
    const float* w_hh_b = (const float*)d_in[12];
    const float* b_ih_b = (const float*)d_in[13];
    const float* b_hh_b = (const float*)d_in[14];
    const float* fc_w   = (const float*)d_in[15];
    const float* fc_b   = (const float*)d_in[16];
    float* out = (float*)d_out;

    // K1: vocabulary-deduped linear: c_table[v] = emb[v] @ w_lin.T + b_lin
    {
        dim3 grid(1, (V_ + 127) / 128);
        gemm_nt_kernel<<<grid, 256>>>(emb, w_lin, w_lin, 128, 128,
                                      b_lin, b_lin, V_, 0);
    }
    // K2: gather + subtree sums + per-tree max pool
    tree_kernel<<<NT_, 128>>>(tokens);

    // K3: input gates for both GRU directions in one GEMM
    {
        dim3 grid(5, NT_ / 128);
        gemm_nt_kernel<<<grid, 256>>>(nullptr, w_ih_f, w_ih_b, 300, 600,
                                      b_ih_f, b_ih_b, NT_, 1);
    }
    // K4: serial recurrence
    gru_kernel<<<128, 320>>>(w_hh_f, w_hh_b, b_hh_f, b_hh_b);

    // K5: final FC
    fc_kernel<<<104, 64>>>(fc_w, fc_b, out);
}

// round 16
// speedup vs baseline: 1.4673x; 1.1677x over previous
#include <cuda_runtime.h>
#include <math.h>

// ---- problem dims ----
#define B_   64
#define S_   200
#define T_   32
#define V_   50000
#define E_   128
#define C_   128
#define H_   100
#define OUT_ 104
#define NT_  (B_*S_)  // 12800 trees
#define N_   (NT_*T_) // 409600 nodes

typedef unsigned long long u64;

// ---- packed f32x2 helpers (Blackwell FFMA2 path) ----
#define FMA2(d, a, b, c) \
    asm("fma.rn.f32x2 %0, %1, %2, %3;" : "=l"(d) : "l"(a), "l"(b), "l"(c))
#define ADD2(d, a, b) \
    asm("add.rn.f32x2 %0, %1, %2;" : "=l"(d) : "l"(a), "l"(b))

__device__ __forceinline__ u64 dup2(float x) {
    u64 r;
    asm("mov.b64 %0, {%1, %1};" : "=l"(r) : "r"(__float_as_uint(x)));
    return r;
}
__device__ __forceinline__ float2 unpack2(u64 v) {
    unsigned lo, hi;
    asm("mov.b64 {%0, %1}, %2;" : "=r"(lo), "=r"(hi) : "l"(v));
    return make_float2(__uint_as_float(lo), __uint_as_float(hi));
}

// ---- device scratch (no allocations allowed) ----
__device__ __align__(16) float g_ctable[V_ * C_];   // W*emb(v)+b per vocab entry
__device__ __align__(16) float g_treevec[NT_ * C_]; // per-tree max-pooled hidden
__device__ __align__(16) float g_gx[NT_ * 600];     // [s*64+b][600] input gates
__device__ __align__(16) float g_poolT[200 * 64];   // [2H][B] transposed pool

// ============================================================================
// GEMM (NT): C[m,n] = sum_k A[m,k]*B[n,k] + bias[n].  K fixed at 128.
// EXACT R2 configuration (BM=128, BN=64, BK=32, 256 threads, 8m x 4n,
// f32x2-packed along m) + register-prefetch double buffering: the next
// k-tile's global loads are issued before the compute loop so L2 latency
// overlaps the 32-kk FMA2 stream.
// mode 0: A=A_in (emb), out -> g_ctable[m*128+n]
// mode 1: A=g_treevec, B=w_ih_f/w_ih_b split at 300, out -> g_gx scattered
// ============================================================================
__global__ void __launch_bounds__(256) gemm_nt_kernel(
    const float* __restrict__ A_in,
    const float* __restrict__ B1, const float* __restrict__ B2, int nsplit,
    int Ncols,
    const float* __restrict__ bias1, const float* __restrict__ bias2,
    int M, int mode)
{
    __shared__ __align__(16) float As[32][132];   // k-major, 128 m cols
    __shared__ __align__(16) float Bs[32][68];    // k-major, 64 n cols

    const float* __restrict__ A = (mode == 0) ? A_in : g_treevec;

    const int m0 = blockIdx.y * 128;
    const int n0 = blockIdx.x * 64;
    const int tid = threadIdx.x;
    const int tx = tid & 15;       // n: 4 per thread
    const int ty = tid >> 4;       // m: 8 per thread

    u64 acc[4][4];                 // [m-pair][n]
    #pragma unroll
    for (int i = 0; i < 4; i++)
        #pragma unroll
        for (int j = 0; j < 4; j++) acc[i][j] = 0ull;

    // ---- per-thread load slots (fixed across k) ----
    int arow[4], akq[4];
    #pragma unroll
    for (int i = 0; i < 4; i++) {
        int f = tid + i * 256;     // 0..1023 float4 slots of A tile
        arow[i] = f >> 3;          // 0..127
        akq[i]  = f & 7;
    }
    int brow[2], bkq[2];
    #pragma unroll
    for (int i = 0; i < 2; i++) {
        int f = tid + i * 256;     // 0..511 float4 slots of B tile
        brow[i] = f >> 3;          // 0..63
        bkq[i]  = f & 7;
    }
    const float* bptr[2];
    bool bok[2];
    #pragma unroll
    for (int i = 0; i < 2; i++) {
        int n = n0 + brow[i];
        bok[i] = (n < Ncols);
        bptr[i] = bok[i] ? ((n < nsplit) ? (B1 + (size_t)n * 128)
                                         : (B2 + (size_t)(n - nsplit) * 128))
                         : B1;
    }

    // ---- prefetch k0 = 0 tile into registers ----
    float4 pa[4], pb[2];
    #pragma unroll
    for (int i = 0; i < 4; i++) {
        int m = m0 + arow[i];
        pa[i] = (m < M) ? *(const float4*)(A + (size_t)m * 128 + akq[i] * 4)
                        : make_float4(0.f, 0.f, 0.f, 0.f);
    }
    #pragma unroll
    for (int i = 0; i < 2; i++)
        pb[i] = bok[i] ? *(const float4*)(bptr[i] + bkq[i] * 4)
                       : make_float4(0.f, 0.f, 0.f, 0.f);

    for (int k0 = 0; k0 < 128; k0 += 32) {
        // ---- commit prefetched tile to smem (k-major transpose) ----
        #pragma unroll
        for (int i = 0; i < 4; i++) {
            As[akq[i]*4+0][arow[i]] = pa[i].x;
            As[akq[i]*4+1][arow[i]] = pa[i].y;
            As[akq[i]*4+2][arow[i]] = pa[i].z;
            As[akq[i]*4+3][arow[i]] = pa[i].w;
        }
        #pragma unroll
        for (int i = 0; i < 2; i++) {
            Bs[bkq[i]*4+0][brow[i]] = pb[i].x;
            Bs[bkq[i]*4+1][brow[i]] = pb[i].y;
            Bs[bkq[i]*4+2][brow[i]] = pb[i].z;
            Bs[bkq[i]*4+3][brow[i]] = pb[i].w;
        }
        __syncthreads();

        // ---- issue next tile's loads (latency hidden under compute) ----
        if (k0 < 96) {
            int kn = k0 + 32;
            #pragma unroll
            for (int i = 0; i < 4; i++) {
                int m = m0 + arow[i];
                pa[i] = (m < M)
                      ? *(const float4*)(A + (size_t)m * 128 + kn + akq[i] * 4)
                      : make_float4(0.f, 0.f, 0.f, 0.f);
            }
            #pragma unroll
            for (int i = 0; i < 2; i++)
                pb[i] = bok[i]
                      ? *(const float4*)(bptr[i] + kn + bkq[i] * 4)
                      : make_float4(0.f, 0.f, 0.f, 0.f);
        }

        #pragma unroll
        for (int kk = 0; kk < 32; kk++) {
            ulonglong2 ap0 = *(const ulonglong2*)&As[kk][ty * 8];
            ulonglong2 ap1 = *(const ulonglong2*)&As[kk][ty * 8 + 4];
            float4 bv = *(const float4*)&Bs[kk][tx * 4];
            u64 bd[4] = { dup2(bv.x), dup2(bv.y), dup2(bv.z), dup2(bv.w) };
            u64 ap[4] = { ap0.x, ap0.y, ap1.x, ap1.y };
            #pragma unroll
            for (int mp = 0; mp < 4; mp++)
                #pragma unroll
                for (int jj = 0; jj < 4; jj++)
                    FMA2(acc[mp][jj], ap[mp], bd[jj], acc[mp][jj]);
        }
        __syncthreads();
    }

    // ---- epilogue: float4 stores per row (identical to R2) ----
    int nbase = n0 + tx * 4;
    bool nok = (nbase < Ncols);
    float4 bias4 = make_float4(0.f, 0.f, 0.f, 0.f);
    if (nok) {
        const float* bp = (nbase < nsplit) ? (bias1 + nbase)
                                           : (bias2 + (nbase - nsplit));
        bias4 = make_float4(bp[0], bp[1], bp[2], bp[3]);
    }
    #pragma unroll
    for (int mp = 0; mp < 4; mp++) {
        float2 c0 = unpack2(acc[mp][0]);
        float2 c1 = unpack2(acc[mp][1]);
        float2 c2 = unpack2(acc[mp][2]);
        float2 c3 = unpack2(acc[mp][3]);
        float4 rlo = make_float4(c0.x + bias4.x, c1.x + bias4.y,
                                 c2.x + bias4.z, c3.x + bias4.w);
        float4 rhi = make_float4(c0.y + bias4.x, c1.y + bias4.y,
                                 c2.y + bias4.z, c3.y + bias4.w);
        int m = m0 + ty * 8 + 2 * mp;
        #pragma unroll
        for (int half = 0; half < 2; half++) {
            int mm = m + half;
            if (mm >= M || !nok) continue;
            float4 r = half ? rhi : rlo;
            if (mode == 0) {
                *(float4*)(g_ctable + (size_t)mm * 128 + nbase) = r;
            } else {
                int s = mm % 200;     // tree mm = b*200 + s
                int b = mm / 200;
                *(float4*)(g_gx + (size_t)(s * 64 + b) * 600 + nbase) = r;
            }
        }
    }
}

// ============================================================================
// Tree encode, float2 version: 64 threads/tree, thread = channel pair.
// Gather 32 rows as LDG.64, subtree sums with packed add.rn.f32x2, max pool
// componentwise. Halves LDG warp-instructions + addressing ALU vs the
// 128-thread scalar version (which profiled alu=47%, issue=58%).
// ============================================================================
__global__ void __launch_bounds__(64) tree_kernel(const int* __restrict__ tokens)
{
    const int tree = blockIdx.x;
    const int c = threadIdx.x;          // 0..63 -> channels 2c, 2c+1
    __shared__ int tok[32];
    if (c < 32) tok[c] = tokens[tree * 32 + c];
    __syncthreads();

    u64 v[32];
    #pragma unroll
    for (int i = 0; i < 32; i++)
        v[i] = *(const u64*)(g_ctable + (size_t)tok[i] * 128 + c * 2);

    // bottom-up subtree sums (fixed complete-binary-tree topology)
    #pragma unroll
    for (int i = 31; i >= 1; i--)
        ADD2(v[(i - 1) >> 1], v[(i - 1) >> 1], v[i]);

    float2 m = unpack2(v[0]);
    #pragma unroll
    for (int i = 1; i < 32; i++) {
        float2 f = unpack2(v[i]);
        m.x = fmaxf(m.x, f.x);
        m.y = fmaxf(m.y, f.y);
    }

    *(float2*)(g_treevec + (size_t)tree * 128 + c * 2) = m;
}

// ============================================================================
// GRU recurrence — EXACT R2 source (best measured: 136.2us).
// 128 blocks = (dir, batch). Thread j<300 owns W_hh row j as 50 packed f32x2
// in registers; h broadcast from smem via LDS.128. 4 packed accumulators.
// Time-max folded in; pool written transposed.
// ============================================================================
__global__ void __launch_bounds__(320) gru_kernel(
    const float* __restrict__ whh_f, const float* __restrict__ whh_b,
    const float* __restrict__ bhh_f, const float* __restrict__ bhh_b)
{
    const int blk = blockIdx.x;     // 0..127
    const int dir = blk >> 6;       // 0 fwd, 1 bwd
    const int b   = blk & 63;
    const int j   = threadIdx.x;    // active < 300

    __shared__ __align__(16) float h_s[100];
    __shared__ float gh_s[300];
    __shared__ float gxn_s[100];

    const float* __restrict__ whh = dir ? whh_b : whh_f;
    const float* __restrict__ bhh = dir ? bhh_b : bhh_f;

    u64 w2[50];
    float bh = 0.f;
    if (j < 300) {
        const u64* wrow = (const u64*)(whh + j * 100);  // 8B-aligned (400j)
        #pragma unroll
        for (int k = 0; k < 50; k++) w2[k] = wrow[k];
        bh = bhh[j];
    }
    if (j < 100) h_s[j] = 0.f;
    float mx = -1e30f;

    // prefetch gx for first step
    int s0 = dir ? 199 : 0;
    float gx_next = 0.f;
    if (j < 300) gx_next = g_gx[(size_t)(s0 * 64 + b) * 600 + dir * 300 + j];
    __syncthreads();

    const ulonglong2* h2 = (const ulonglong2*)h_s;

    #pragma unroll 1
    for (int sp = 0; sp < 200; sp++) {
        float gxv = gx_next;
        if (sp < 199 && j < 300) {
            int sn = dir ? (198 - sp) : (sp + 1);
            gx_next = g_gx[(size_t)(sn * 64 + b) * 600 + dir * 300 + j];
        }
        if (j < 300) {
            u64 a0 = 0ull, a1 = 0ull, a2 = 0ull, a3 = 0ull;
            #pragma unroll
            for (int k = 0; k < 25; k++) {
                ulonglong2 hv = h2[k];
                if (k & 1) {
                    FMA2(a2, w2[2*k],   hv.x, a2);
                    FMA2(a3, w2[2*k+1], hv.y, a3);
                } else {
                    FMA2(a0, w2[2*k],   hv.x, a0);
                    FMA2(a1, w2[2*k+1], hv.y, a1);
                }
            }
            ADD2(a0, a0, a2);
            ADD2(a1, a1, a3);
            ADD2(a0, a0, a1);
            float2 f = unpack2(a0);
            float acc = f.x + f.y + bh;
            if (j < 200) {
                float x = gxv + acc;                 // r,z rows
                gh_s[j] = 1.f / (1.f + __expf(-x));  // sigmoid
            } else {
                gh_s[j] = acc;                       // raw hn
                gxn_s[j - 200] = gxv;                // stash xn
            }
        }
        __syncthreads();
        if (j < 100) {
            float r = gh_s[j];
            float z = gh_s[j + 100];
            float n = tanhf(gxn_s[j] + r * gh_s[j + 200]);
            float hn = fmaf(z, h_s[j] - n, n);       // (1-z)n + z h
            h_s[j] = hn;
            mx = fmaxf(mx, hn);
        }
        __syncthreads();
    }

    if (j < 100) g_poolT[(dir * 100 + j) * 64 + b] = mx;
}

// ============================================================================
// Final FC: out[b,o] = pool[b,:] . fc_w[o,:] + fc_b[o]
// ============================================================================
__global__ void __launch_bounds__(64) fc_kernel(
    const float* __restrict__ fcw, const float* __restrict__ fcb,
    float* __restrict__ out)
{
    const int o = blockIdx.x;   // 0..103
    const int b = threadIdx.x;  // 0..63
    __shared__ float w_s[200];
    for (int k = b; k < 200; k += 64) w_s[k] = fcw[o * 200 + k];
    __syncthreads();

    float acc = fcb[o];
    #pragma unroll
    for (int k = 0; k < 200; k++)
        acc = fmaf(w_s[k], g_poolT[k * 64 + b], acc);

    out[b * 104 + o] = acc;
}

// ============================================================================
extern "C" void kernel_launch(void* const* d_in, const int* in_sizes, int n_in,
                              void* d_out, int out_size)
{
    const int*   tokens = (const int*)  d_in[0];
    const float* emb    = (const float*)d_in[4];
    const float* w_lin  = (const float*)d_in[5];
    const float* b_lin  = (const float*)d_in[6];
    const float* w_ih_f = (const float*)d_in[7];
    const float* w_hh_f = (const float*)d_in[8];
    const float* b_ih_f = (const float*)d_in[9];
    const float* b_hh_f = (const float*)d_in[10];
    const float* w_ih_b = (const float*)d_in[11];
    const float* w_hh_b = (const float*)d_in[12];
    const float* b_ih_b = (const float*)d_in[13];
    const float* b_hh_b = (const float*)d_in[14];
    const float* fc_w   = (const float*)d_in[15];
    const float* fc_b   = (const float*)d_in[16];
    float* out = (float*)d_out;

    // K1: vocabulary-deduped linear: c_table[v] = emb[v] @ w_lin.T + b_lin
    {
        dim3 grid(2, (V_ + 127) / 128);
        gemm_nt_kernel<<<grid, 256>>>(emb, w_lin, w_lin, 128, 128,
                                      b_lin, b_lin, V_, 0);
    }
    // K2: gather + subtree sums + per-tree max pool (float2 threads)
    tree_kernel<<<NT_, 64>>>(tokens);

    // K3: input gates for both GRU directions in one GEMM
    {
        dim3 grid(10, NT_ / 128);
        gemm_nt_kernel<<<grid, 256>>>(nullptr, w_ih_f, w_ih_b, 300, 600,
                                      b_ih_f, b_ih_b, NT_, 1);
    }
    // K4: serial recurrence (exact R2)
    gru_kernel<<<128, 320>>>(w_hh_f, w_hh_b, b_hh_f, b_hh_b);

    // K5: final FC
    fc_kernel<<<104, 64>>>(fc_w, fc_b, out);
}